// round 2
// baseline (speedup 1.0000x reference)
#include <cuda_runtime.h>
#include <cuda_bf16.h>
#include <cstdint>

// out[n] = prod_f sigmoid(10*(x[n,f]*w[f] + b[f]))^(1/2)
//        = rsqrt( prod_f (1 + exp(-10*(x*w + b))) )
//        = rsqrt( prod_f (1 + 2^(c_f * x + d_f)) )
// with c_f = -10*w_f*log2(e), d_f = -10*b_f*log2(e).

#define F 64
#define PAIRS_PER_WARP 4
#define THREADS 256

__device__ __forceinline__ float ex2f(float x) {
    float r;
    asm("ex2.approx.f32 %0, %1;" : "=f"(r) : "f"(x));
    return r;
}

__global__ void __launch_bounds__(THREADS)
onetoone_kernel(const float4* __restrict__ x4,
                const float4* __restrict__ w4,
                const float4* __restrict__ b4,
                float* __restrict__ out,
                int total_pairs)   // total_pairs = n_rows / 2
{
    const int lane = threadIdx.x & 31;
    const int j    = lane & 15;   // which float4 within the row (16 x float4 = 64 floats)
    const int half = lane >> 4;   // which row of the pair
    const int gwarp = (int)((blockIdx.x * (unsigned)blockDim.x + threadIdx.x) >> 5);
    const int base_pair = gwarp * PAIRS_PER_WARP;

    // Per-lane folded coefficients (constant across all rows this lane touches)
    const float S = -10.0f * 1.4426950408889634f;   // -scale * log2(e)
    float4 wv = __ldg(&w4[j]);
    float4 bv = __ldg(&b4[j]);
    const float c0 = S * wv.x, c1 = S * wv.y, c2 = S * wv.z, c3 = S * wv.w;
    const float d0 = S * bv.x, d1 = S * bv.y, d2 = S * bv.z, d3 = S * bv.w;

    // Front-batched loads: MLP = PAIRS_PER_WARP per thread
    float4 xv[PAIRS_PER_WARP];
    bool   ok[PAIRS_PER_WARP];
#pragma unroll
    for (int i = 0; i < PAIRS_PER_WARP; i++) {
        int pair = base_pair + i;
        ok[i] = (pair < total_pairs);
        if (ok[i]) {
            int row = pair * 2 + half;
            xv[i] = x4[row * (F / 4) + j];
        }
    }

#pragma unroll
    for (int i = 0; i < PAIRS_PER_WARP; i++) {
        // predicate guard (no break: keeps the loop fully unrolled, no BSSY/BSYNC)
        if (ok[i]) {
            int pair = base_pair + i;
            int row  = pair * 2 + half;

            float t0 = fmaf(c0, xv[i].x, d0);
            float t1 = fmaf(c1, xv[i].y, d1);
            float t2 = fmaf(c2, xv[i].z, d2);
            float t3 = fmaf(c3, xv[i].w, d3);

            // lane-local product of 4 terms (each in (1, ~2^10+1]; bounded ~2^40)
            float p = ((1.0f + ex2f(t0)) * (1.0f + ex2f(t1))) *
                      ((1.0f + ex2f(t2)) * (1.0f + ex2f(t3)));

            // product over 8 lanes (32 terms) — still far from fp32 overflow
            p *= __shfl_xor_sync(0xFFFFFFFFu, p, 1);
            p *= __shfl_xor_sync(0xFFFFFFFFu, p, 2);
            p *= __shfl_xor_sync(0xFFFFFFFFu, p, 4);

            // sqrt-domain BEFORE the last combine so the full 64-term product
            // (mean ~e^58, tail toward fp32 overflow) never materializes.
            float q = rsqrtf(p);
            q *= __shfl_xor_sync(0xFFFFFFFFu, q, 8);

            if (j == 0) out[row] = q;
        }
    }
}

extern "C" void kernel_launch(void* const* d_in, const int* in_sizes, int n_in,
                              void* d_out, int out_size)
{
    const float* x = (const float*)d_in[0];
    const float* w = (const float*)d_in[1];
    const float* b = (const float*)d_in[2];
    float* out = (float*)d_out;

    int n_rows = in_sizes[0] / F;          // 2,097,152
    int total_pairs = (n_rows + 1) / 2;    // 1,048,576

    int warps_needed = (total_pairs + PAIRS_PER_WARP - 1) / PAIRS_PER_WARP;
    int warps_per_block = THREADS / 32;
    int blocks = (warps_needed + warps_per_block - 1) / warps_per_block;

    onetoone_kernel<<<blocks, THREADS>>>((const float4*)x,
                                         (const float4*)w,
                                         (const float4*)b,
                                         out, total_pairs);
}